// round 16
// baseline (speedup 1.0000x reference)
#include <cuda_runtime.h>
#include <cuda_fp16.h>
#include <cstdint>

// TriangleMultiplication, mma.sync m16n8k16 fp16, split-fp16 fp32 emu.
// R16 = R15 + tri and out FUSED: h tile (split hi/lo) lives in a 128KB SMEM
// image between the two GEMMs, deleting the 256MB H DRAM round-trip. Phase 1:
// 2x narrow single-pass tri GEMM + gate -> smem. Phase 2: 2x 2-pass out GEMM
// with A fragments from smem, Wo streamed via an 8KB ring. Numerics identical
// to R15 (rel_err should reproduce ~5.3e-4).

#define THREADS 256
// narrow ring (proj + fused phase1): A 8KB hi-only + B 8KB per stage
#define OFF_B1  8192
#define STAGE1  16384
#define NSTAGE  3
// proj-kernel barrier base & smem (stage region + b-transpose staging overlap)
#define OFF_MBP 73728
#define SMEM_P  73792
// fused-kernel layout: rings [0,49152), barriers at 49152, h image at 49280
#define OFF_MBF 49152
#define OFF_HIMG 49280
#define SMEM_F  180352               // 49280 + 128KB h image

#define NELEM 33554432            // 2*256*256*256
#define HCH 8388608UL             // narrow k-chunk stride (131072 rows * 64B)
#define BCH 16384UL               // B-family k-chunk stride (256 rows * 64B)
#define SLB 131072UL              // per-slice / per-weight B bytes (8 chunks)

// narrow hi-only images [kc8][m][64B]
static __device__ __align__(16) __half g_P[NELEM];
static __device__ __align__(16) __half g_A[NELEM];
// B-family hi-only images [.][kc8][row 256][64B]
static __device__ __align__(16) __half g_B[NELEM];
static __device__ __align__(16) __half g_W[4*65536];
static __device__ float g_G[NELEM];   // sigmoid gate fp32 natural [m][l]

__device__ __forceinline__ uint32_t pack_h2(__half x, __half y) {
    __half2 t = __halves2half2(x, y);
    return *reinterpret_cast<uint32_t*>(&t);
}
__device__ __forceinline__ uint32_t smem_u32(const void* p) {
    uint32_t a;
    asm("{ .reg .u64 t; cvta.to.shared.u64 t, %1; cvt.u32.u64 %0, t; }" : "=r"(a) : "l"(p));
    return a;
}
__device__ __forceinline__ void mma16816(float d[4], const uint32_t a[4], const uint32_t b[2]) {
    asm volatile(
        "mma.sync.aligned.m16n8k16.row.col.f32.f16.f16.f32 "
        "{%0,%1,%2,%3}, {%4,%5,%6,%7}, {%8,%9}, {%0,%1,%2,%3};"
        : "+f"(d[0]), "+f"(d[1]), "+f"(d[2]), "+f"(d[3])
        : "r"(a[0]), "r"(a[1]), "r"(a[2]), "r"(a[3]), "r"(b[0]), "r"(b[1]));
}
__device__ __forceinline__ void ldsm_x4(uint32_t r[4], uint32_t a) {
    asm volatile("ldmatrix.sync.aligned.m8n8.x4.shared.b16 {%0,%1,%2,%3}, [%4];"
        : "=r"(r[0]), "=r"(r[1]), "=r"(r[2]), "=r"(r[3]) : "r"(a));
}
__device__ __forceinline__ void split2(float x, float y, uint32_t& H, uint32_t& L) {
    __half hx = __float2half_rn(x), hy = __float2half_rn(y);
    __half lx = __float2half_rn(x - __half2float(hx));
    __half ly = __float2half_rn(y - __half2float(hy));
    H = pack_h2(hx, hy); L = pack_h2(lx, ly);
}

#define MBAR_INIT(a, n) asm volatile("mbarrier.init.shared.b64 [%0], %1;" :: "r"(a), "r"(n) : "memory")
#define MBAR_EXPECT(a, b) asm volatile("mbarrier.arrive.expect_tx.shared.b64 _, [%0], %1;" :: "r"(a), "r"(b) : "memory")
#define MBAR_ARRIVE(a) asm volatile("mbarrier.arrive.shared.b64 _, [%0];" :: "r"(a) : "memory")
#define MBAR_WAIT(a, ph) do { \
    uint32_t _m = (a), _p = (ph), _d; \
    asm volatile("{ .reg .pred p; mbarrier.try_wait.parity.acquire.cta.shared::cta.b64 p, [%1], %2; selp.b32 %0,1,0,p; }" \
        : "=r"(_d) : "r"(_m), "r"(_p) : "memory"); \
    if (!_d) { \
        asm volatile("{ .reg .pred P1; WL_%=: mbarrier.try_wait.parity.acquire.cta.shared::cta.b64 P1, [%0], %1, 0x989680; @P1 bra.uni WD_%=; bra.uni WL_%=; WD_%=: }" \
            :: "r"(_m), "r"(_p) : "memory"); \
    } } while (0)

__device__ __forceinline__ void bulk_cp(uint32_t dst, const char* src, uint32_t bytes, uint32_t mb) {
    asm volatile("cp.async.bulk.shared::cluster.global.mbarrier::complete_tx::bytes [%0], [%1], %2, [%3];"
        :: "r"(dst), "l"(src), "r"(bytes), "r"(mb) : "memory");
}

// wide (h-image) rows 128B: chunk xor key r&7
__device__ __forceinline__ uint32_t inrowA(int r, int b) {
    return (uint32_t)(((((b >> 4) ^ (r & 7)) << 4)) | (b & 15));
}
// narrow rows 64B: chunk xor key (r>>1)&3
__device__ __forceinline__ uint32_t inrowB(int r, int b) {
    return (uint32_t)(((((b >> 4) ^ ((r >> 1) & 3)) << 4)) | (b & 15));
}
__device__ __forceinline__ size_t off_b(int row, int k) {       // B-family (256-row chunks)
    return (size_t)(k >> 5) * BCH + (size_t)row * 64 + inrowB(row, (k & 31) * 2);
}
__device__ __forceinline__ size_t off_n(int row, int k) {       // narrow (131072-row chunks)
    return (size_t)(k >> 5) * HCH + (size_t)row * 64 + inrowB(row, (k & 31) * 2);
}
// split store into the SMEM h image (wide layout, 16KB chunks, local rows)
__device__ __forceinline__ void store_h_smem(char* hbase, int lrow, int k, float x, float y) {
    uint32_t H, L; split2(x, y, H, L);
    char* row = hbase + (size_t)((k >> 5) * 16384 + lrow * 128);
    *(uint32_t*)(row + inrowA(lrow, (k & 31) * 2)) = H;
    *(uint32_t*)(row + inrowA(lrow, 64 + (k & 31) * 2)) = L;
}

// ---------------- narrow GEMM (proj / fused phase1): A hi-only, 1-pass -------

__device__ __forceinline__ void issue_chunk1(uint32_t sb, uint32_t mb, int st,
    const char* Aimg, const char* Bimg, int c)
{
    const uint32_t buf = sb + (uint32_t)st * STAGE1;
    MBAR_EXPECT(mb + st * 8, 16384u);
    bulk_cp(buf,          Aimg + (size_t)c * HCH, 8192, mb + st * 8);
    bulk_cp(buf + OFF_B1, Bimg + (size_t)c * BCH, 8192, mb + st * 8);
}

__device__ __forceinline__ void gemm_compute1(uint32_t sb, uint32_t mb,
    const char* __restrict__ Aimg, const char* __restrict__ Bimg,
    float acc[2][8][4])
{
    const int tid = threadIdx.x;
    const int lane = tid & 31, wid = tid >> 5;
    const int wm = wid >> 1, wn = wid & 1;

#pragma unroll
    for (int mt = 0; mt < 2; ++mt)
#pragma unroll
        for (int nt = 0; nt < 8; ++nt)
#pragma unroll
            for (int i = 0; i < 4; ++i) acc[mt][nt][i] = 0.f;

    __syncthreads();   // prior use of rings/barriers fully drained
    if (tid == 0) {
#pragma unroll
        for (int s = 0; s < NSTAGE; ++s) {
            MBAR_INIT(mb + s * 8, 1);
            MBAR_INIT(mb + 24 + s * 8, 8);
        }
    }
    __syncthreads();
    if (tid == 0) {
        issue_chunk1(sb, mb, 0, Aimg, Bimg, 0);
        issue_chunk1(sb, mb, 1, Aimg, Bimg, 1);
    }

    const uint32_t a_base = (uint32_t)(wm*32 + (lane & 15)) * 64;
    const uint32_t a_kh   = lane >> 4;
    const uint32_t axr    = (lane >> 1) & 3;
    const uint32_t b_row  = (lane & 7) + ((lane & 16) >> 1);
    const uint32_t b_base = ((uint32_t)(wn*64) + b_row) * 64;
    const uint32_t b_kh   = (lane >> 3) & 1;
    const uint32_t bxr    = (lane & 6) >> 1;

#pragma unroll
    for (int c = 0; c < 8; ++c) {
        const int st = c % NSTAGE;
        if (tid == 0 && c + 2 < 8) {
            const int cn = c + 2, st2 = cn % NSTAGE;
            if (cn >= NSTAGE) { MBAR_WAIT(mb + 24 + st2 * 8, ((cn - NSTAGE) / NSTAGE) & 1); }
            issue_chunk1(sb, mb, st2, Aimg, Bimg, cn);
        }
        MBAR_WAIT(mb + st * 8, (c / NSTAGE) & 1);
        const uint32_t buf = sb + (uint32_t)st * STAGE1;
#pragma unroll
        for (int s = 0; s < 2; ++s) {
            const uint32_t ax = (((uint32_t)s*2 + a_kh) ^ axr) << 4;
            const uint32_t bx = (((uint32_t)s*2 + b_kh) ^ bxr) << 4;
            uint32_t ah[2][4];
#pragma unroll
            for (int mt = 0; mt < 2; ++mt)
                ldsm_x4(ah[mt], buf + a_base + (uint32_t)mt*1024 + ax);
#pragma unroll
            for (int half = 0; half < 2; ++half) {
                uint32_t bh[2][4];
#pragma unroll
                for (int p = 0; p < 2; ++p) {
                    const uint32_t bo = buf + OFF_B1 + b_base + (uint32_t)(half*2 + p)*1024;
                    ldsm_x4(bh[p], bo + bx);
                }
#pragma unroll
                for (int mt = 0; mt < 2; ++mt)
#pragma unroll
                    for (int p = 0; p < 2; ++p)
#pragma unroll
                        for (int q = 0; q < 2; ++q)
                            mma16816(acc[mt][half*4 + p*2 + q], ah[mt], &bh[p][q*2]);
            }
        }
        if (lane == 0) MBAR_ARRIVE(mb + 24 + st * 8);
    }
}

// -------- smem-A GEMM (fused phase2): A split from h image, 2-pass ----------

__device__ __forceinline__ void issue_chunkB(uint32_t sb, uint32_t mb, int st,
    const char* Bimg, int c)
{
    MBAR_EXPECT(mb + st * 8, 8192u);
    bulk_cp(sb + (uint32_t)st * 8192, Bimg + (size_t)c * BCH, 8192, mb + st * 8);
}

__device__ __forceinline__ void gemm_smemA(uint32_t sb, uint32_t mb, uint32_t himg,
    const char* __restrict__ Bimg, float acc[2][8][4])
{
    const int tid = threadIdx.x;
    const int lane = tid & 31, wid = tid >> 5;
    const int wm = wid >> 1, wn = wid & 1;

#pragma unroll
    for (int mt = 0; mt < 2; ++mt)
#pragma unroll
        for (int nt = 0; nt < 8; ++nt)
#pragma unroll
            for (int i = 0; i < 4; ++i) acc[mt][nt][i] = 0.f;

    __syncthreads();   // h-image writes + prior ring use complete
    if (tid == 0) {
#pragma unroll
        for (int s = 0; s < NSTAGE; ++s) {
            MBAR_INIT(mb + s * 8, 1);
            MBAR_INIT(mb + 24 + s * 8, 8);
        }
    }
    __syncthreads();
    if (tid == 0) {
        issue_chunkB(sb, mb, 0, Bimg, 0);
        issue_chunkB(sb, mb, 1, Bimg, 1);
    }

    const uint32_t xr     = lane & 7;
    const uint32_t a_base = (uint32_t)(wm*32 + (lane & 15)) * 128;
    const uint32_t a_kh   = lane >> 4;
    const uint32_t b_row  = (lane & 7) + ((lane & 16) >> 1);
    const uint32_t b_base = ((uint32_t)(wn*64) + b_row) * 64;
    const uint32_t b_kh   = (lane >> 3) & 1;
    const uint32_t bxr    = (lane & 6) >> 1;

#pragma unroll
    for (int c = 0; c < 8; ++c) {
        const int st = c % NSTAGE;
        if (tid == 0 && c + 2 < 8) {
            const int cn = c + 2, st2 = cn % NSTAGE;
            if (cn >= NSTAGE) { MBAR_WAIT(mb + 24 + st2 * 8, ((cn - NSTAGE) / NSTAGE) & 1); }
            issue_chunkB(sb, mb, st2, Bimg, cn);
        }
        MBAR_WAIT(mb + st * 8, (c / NSTAGE) & 1);
        const uint32_t bufB = sb + (uint32_t)st * 8192;
        const uint32_t abuf = himg + (uint32_t)c * 16384;
#pragma unroll
        for (int s = 0; s < 2; ++s) {
            const uint32_t ach = (uint32_t)s*2 + a_kh;
            const uint32_t ax_h = ((ach ^ xr) << 4), ax_l = (((ach + 4) ^ xr) << 4);
            const uint32_t bx   = (((uint32_t)s*2 + b_kh) ^ bxr) << 4;
            uint32_t ah[2][4], al[2][4];
#pragma unroll
            for (int mt = 0; mt < 2; ++mt) {
                const uint32_t ao = abuf + a_base + (uint32_t)mt*2048;
                ldsm_x4(ah[mt], ao + ax_h);
                ldsm_x4(al[mt], ao + ax_l);
            }
#pragma unroll
            for (int half = 0; half < 2; ++half) {
                uint32_t bh[2][4];
#pragma unroll
                for (int p = 0; p < 2; ++p) {
                    const uint32_t bo = bufB + b_base + (uint32_t)(half*2 + p)*1024;
                    ldsm_x4(bh[p], bo + bx);
                }
#pragma unroll
                for (int mt = 0; mt < 2; ++mt)
#pragma unroll
                    for (int p = 0; p < 2; ++p)
#pragma unroll
                        for (int q = 0; q < 2; ++q)
                            mma16816(acc[mt][half*4 + p*2 + q], ah[mt], &bh[p][q*2]);
#pragma unroll
                for (int mt = 0; mt < 2; ++mt)
#pragma unroll
                    for (int p = 0; p < 2; ++p)
#pragma unroll
                        for (int q = 0; q < 2; ++q)
                            mma16816(acc[mt][half*4 + p*2 + q], al[mt], &bh[p][q*2]);
            }
        }
        if (lane == 0) MBAR_ARRIVE(mb + 24 + st * 8);
    }
}

// ---------------- prep kernels ----------------

extern "C" __global__ void psplit_kernel(const float* __restrict__ pair)
{
    const size_t i = ((size_t)blockIdx.x * 256 + threadIdx.x) * 4;
    const int m = (int)(i >> 8), col = (int)(i & 255);
    float4 v = *(const float4*)(pair + i);
    uint32_t h01 = pack_h2(__float2half_rn(v.x), __float2half_rn(v.y));
    uint32_t h23 = pack_h2(__float2half_rn(v.z), __float2half_rn(v.w));
    *(uint2*)((char*)g_P + off_n(m, col)) = make_uint2(h01, h23);
}

extern "C" __global__ void wprep_kernel(const float* __restrict__ Wa,
                                        const float* __restrict__ Wb,
                                        const float* __restrict__ Wg,
                                        const float* __restrict__ Wo)
{
    const float* Ws[4] = {Wa, Wb, Wg, Wo};
    const int d = blockIdx.x, c = threadIdx.x;
    const size_t off = off_b(d, c);
#pragma unroll
    for (int w = 0; w < 4; ++w) {
        __half h = __float2half_rn(Ws[w][c*256 + d]);
        *(__half*)((char*)g_W + (size_t)w * SLB + off) = h;
    }
}

// ---------------- GEMM kernels ----------------

// grid (6, 1024): x = w*2 + nt, y = m-tile. Single-pass narrow GEMM.
extern "C" __global__ void __launch_bounds__(THREADS, 2)
proj_kernel(const float* __restrict__ ba, const float* __restrict__ bb,
            const float* __restrict__ bg)
{
    extern __shared__ char smem[];
    const uint32_t sb = smem_u32(smem);
    const int w = blockIdx.x >> 1, nt = blockIdx.x & 1;
    const int m0 = blockIdx.y * 128;

    float acc[2][8][4];
    gemm_compute1(sb, sb + OFF_MBP,
                  (const char*)g_P + (size_t)m0*64,
                  (const char*)g_W + (size_t)w*SLB + (size_t)nt*8192,
                  acc);
    __syncthreads();

    const float* bias = (w == 0) ? ba : ((w == 1) ? bb : bg);
    const int wid = threadIdx.x >> 5, lane = threadIdx.x & 31;
    const int wm = wid >> 1, wn = wid & 1;
    const int g = lane >> 2, qc = lane & 3;

    if (w == 1) {
        float* stg = (float*)smem + wid * 2080;  // 32*65
#pragma unroll
        for (int mt = 0; mt < 2; ++mt)
#pragma unroll
            for (int ntl = 0; ntl < 8; ++ntl) {
                const int rm = mt*16 + g, cn = ntl*8 + 2*qc;
                float2 bv = *(const float2*)(bias + nt*128 + wn*64 + cn);
                stg[rm*65 + cn]           = acc[mt][ntl][0] + bv.x;
                stg[rm*65 + cn + 1]       = acc[mt][ntl][1] + bv.y;
                stg[(rm + 8)*65 + cn]     = acc[mt][ntl][2] + bv.x;
                stg[(rm + 8)*65 + cn + 1] = acc[mt][ntl][3] + bv.y;
            }
        __syncwarp();
        const int slice = m0 >> 8;
        const int j0 = (m0 & 255) + wm * 32;
        const int m2 = 2 * (lane & 15);
        const int j = j0 + m2;
        char* base = (char*)g_B + (size_t)slice * SLB;
        for (int r = lane >> 4; r < 64; r += 2) {
            const int l = nt*128 + wn*64 + r;
            uint32_t H = pack_h2(__float2half_rn(stg[m2*65 + r]),
                                 __float2half_rn(stg[(m2 + 1)*65 + r]));
            *(uint32_t*)(base + off_b(l, j)) = H;
        }
    } else {
#pragma unroll
        for (int mt = 0; mt < 2; ++mt) {
            const int R0 = m0 + wm*32 + mt*16 + g;
#pragma unroll
            for (int ntl = 0; ntl < 8; ++ntl) {
                const int col = nt*128 + wn*64 + ntl*8 + 2*qc;
                float2 bv = *(const float2*)(bias + col);
                float v0 = acc[mt][ntl][0] + bv.x, v1 = acc[mt][ntl][1] + bv.y;
                float v2 = acc[mt][ntl][2] + bv.x, v3 = acc[mt][ntl][3] + bv.y;
                if (w == 2) {
                    v0 = 1.f/(1.f + __expf(-v0)); v1 = 1.f/(1.f + __expf(-v1));
                    v2 = 1.f/(1.f + __expf(-v2)); v3 = 1.f/(1.f + __expf(-v3));
                    *(float2*)(g_G + (size_t)R0*256 + col)       = make_float2(v0, v1);
                    *(float2*)(g_G + (size_t)(R0 + 8)*256 + col) = make_float2(v2, v3);
                } else {
                    *(uint32_t*)((char*)g_A + off_n(R0, col)) =
                        pack_h2(__float2half_rn(v0), __float2half_rn(v1));
                    *(uint32_t*)((char*)g_A + off_n(R0 + 8, col)) =
                        pack_h2(__float2half_rn(v2), __float2half_rn(v3));
                }
            }
        }
    }
}

// grid (2, 512): x = jt, y = slice. Fused tri+out:
//   phase1: h = g*(a_s @ b_s) -> SMEM split image (both lt halves)
//   phase2: out = h @ Wo^T-rows + bo (2-pass from SMEM, both nt halves)
extern "C" __global__ void __launch_bounds__(THREADS)
fused_kernel(const float* __restrict__ bo, float* __restrict__ out)
{
    extern __shared__ char smem[];
    const uint32_t sb = smem_u32(smem);
    const uint32_t mb = sb + OFF_MBF;
    const uint32_t himg = sb + OFF_HIMG;
    char* hptr = smem + OFF_HIMG;
    const int jt = blockIdx.x, slice = blockIdx.y;

    const int wid = threadIdx.x >> 5, lane = threadIdx.x & 31;
    const int wm = wid >> 1, wn = wid & 1;
    const int g = lane >> 2, qc = lane & 3;
    const int mbase = slice*256 + jt*128;

    // ---- phase 1: tri ----
    for (int lt = 0; lt < 2; ++lt) {
        float acc[2][8][4];
        gemm_compute1(sb, mb,
                      (const char*)g_A + (size_t)mbase*64,
                      (const char*)g_B + (size_t)slice*SLB + (size_t)lt*8192,
                      acc);
#pragma unroll
        for (int mt = 0; mt < 2; ++mt) {
            const int lr = wm*32 + mt*16 + g;       // local row in 128-tile
            const int Rg = mbase + lr;              // global row
#pragma unroll
            for (int ntl = 0; ntl < 8; ++ntl) {
                const int col = lt*128 + wn*64 + ntl*8 + 2*qc;
                float2 g0 = *(const float2*)(g_G + (size_t)Rg*256 + col);
                float2 g1 = *(const float2*)(g_G + (size_t)(Rg + 8)*256 + col);
                store_h_smem(hptr, lr,     col, acc[mt][ntl][0]*g0.x, acc[mt][ntl][1]*g0.y);
                store_h_smem(hptr, lr + 8, col, acc[mt][ntl][2]*g1.x, acc[mt][ntl][3]*g1.y);
            }
        }
    }

    // ---- phase 2: out ----
    for (int nt = 0; nt < 2; ++nt) {
        float acc[2][8][4];
        gemm_smemA(sb, mb, himg,
                   (const char*)g_W + (size_t)3*SLB + (size_t)nt*8192,
                   acc);
#pragma unroll
        for (int mt = 0; mt < 2; ++mt) {
            const int R0 = mbase + wm*32 + mt*16 + g;
#pragma unroll
            for (int ntl = 0; ntl < 8; ++ntl) {
                const int col = nt*128 + wn*64 + ntl*8 + 2*qc;
                float2 bv = *(const float2*)(bo + col);
                *(float2*)(out + (size_t)R0*256 + col) =
                    make_float2(acc[mt][ntl][0] + bv.x, acc[mt][ntl][1] + bv.y);
                *(float2*)(out + (size_t)(R0 + 8)*256 + col) =
                    make_float2(acc[mt][ntl][2] + bv.x, acc[mt][ntl][3] + bv.y);
            }
        }
    }
}

extern "C" void kernel_launch(void* const* d_in, const int* in_sizes, int n_in,
                              void* d_out, int out_size)
{
    const float* pair = (const float*)d_in[0];
    const float* Wa   = (const float*)d_in[1];
    const float* ba   = (const float*)d_in[2];
    const float* Wb   = (const float*)d_in[3];
    const float* bb   = (const float*)d_in[4];
    const float* Wg   = (const float*)d_in[5];
    const float* bg   = (const float*)d_in[6];
    const float* Wo   = (const float*)d_in[7];
    const float* bo   = (const float*)d_in[8];
    float* out = (float*)d_out;

    cudaFuncSetAttribute(proj_kernel,  cudaFuncAttributeMaxDynamicSharedMemorySize, SMEM_P);
    cudaFuncSetAttribute(fused_kernel, cudaFuncAttributeMaxDynamicSharedMemorySize, SMEM_F);

    wprep_kernel <<<256,   256>>>(Wa, Wb, Wg, Wo);
    psplit_kernel<<<32768, 256>>>(pair);
    proj_kernel <<<dim3(6, 1024), THREADS, SMEM_P>>>(ba, bb, bg);
    fused_kernel<<<dim3(2, 512),  THREADS, SMEM_F>>>(bo, out);
}

// round 17
// speedup vs baseline: 1.0606x; 1.0606x over previous
#include <cuda_runtime.h>
#include <cuda_fp16.h>
#include <cstdint>

// TriangleMultiplication, mma.sync m16n8k16 fp16, split-fp16 fp32 emu.
// R17 = R16 fusion, but the fused CTA is 512 threads (16 warps, 4/SMSP) with
// a 4x4 warp grid covering the full 128x256 tile in one gemm call per phase
// (restores intra-CTA latency cover lost at 1 CTA/SM), and the gate is fp16.

#define NSTAGE  3
// proj ring (256 thr): A 8KB hi-only + B 8KB
#define OFF_B1  8192
#define STAGE1  16384
#define OFF_MBP 73728
#define SMEM_P  73792
// fused ring (512 thr): A 8KB hi-only + B 16KB full width
#define OFF_BF  8192
#define STAGEF  24576
#define OFF_MBF 73728                 // full[0..2] +0,8,16 ; empty +24,32,40
#define OFF_HIMG 73856                // 128KB split h image (8 x 16KB chunks)
#define SMEM_F  204928

#define NELEM 33554432            // 2*256*256*256
#define HCH 8388608UL             // narrow k-chunk stride (131072 rows * 64B)
#define BCH 16384UL               // B-family k-chunk stride (256 rows * 64B)
#define SLB 131072UL              // per-slice / per-weight B bytes (8 chunks)

// narrow hi-only images [kc8][m][64B]
static __device__ __align__(16) __half g_P[NELEM];
static __device__ __align__(16) __half g_A[NELEM];
// B-family hi-only images [.][kc8][row 256][64B]
static __device__ __align__(16) __half g_B[NELEM];
static __device__ __align__(16) __half g_W[4*65536];
static __device__ __align__(16) __half g_G[NELEM];  // gate fp16 natural [m][l]

__device__ __forceinline__ uint32_t pack_h2(__half x, __half y) {
    __half2 t = __halves2half2(x, y);
    return *reinterpret_cast<uint32_t*>(&t);
}
__device__ __forceinline__ uint32_t smem_u32(const void* p) {
    uint32_t a;
    asm("{ .reg .u64 t; cvta.to.shared.u64 t, %1; cvt.u32.u64 %0, t; }" : "=r"(a) : "l"(p));
    return a;
}
__device__ __forceinline__ void mma16816(float d[4], const uint32_t a[4], const uint32_t b[2]) {
    asm volatile(
        "mma.sync.aligned.m16n8k16.row.col.f32.f16.f16.f32 "
        "{%0,%1,%2,%3}, {%4,%5,%6,%7}, {%8,%9}, {%0,%1,%2,%3};"
        : "+f"(d[0]), "+f"(d[1]), "+f"(d[2]), "+f"(d[3])
        : "r"(a[0]), "r"(a[1]), "r"(a[2]), "r"(a[3]), "r"(b[0]), "r"(b[1]));
}
__device__ __forceinline__ void ldsm_x4(uint32_t r[4], uint32_t a) {
    asm volatile("ldmatrix.sync.aligned.m8n8.x4.shared.b16 {%0,%1,%2,%3}, [%4];"
        : "=r"(r[0]), "=r"(r[1]), "=r"(r[2]), "=r"(r[3]) : "r"(a));
}
__device__ __forceinline__ void split2(float x, float y, uint32_t& H, uint32_t& L) {
    __half hx = __float2half_rn(x), hy = __float2half_rn(y);
    __half lx = __float2half_rn(x - __half2float(hx));
    __half ly = __float2half_rn(y - __half2float(hy));
    H = pack_h2(hx, hy); L = pack_h2(lx, ly);
}

#define MBAR_INIT(a, n) asm volatile("mbarrier.init.shared.b64 [%0], %1;" :: "r"(a), "r"(n) : "memory")
#define MBAR_EXPECT(a, b) asm volatile("mbarrier.arrive.expect_tx.shared.b64 _, [%0], %1;" :: "r"(a), "r"(b) : "memory")
#define MBAR_ARRIVE(a) asm volatile("mbarrier.arrive.shared.b64 _, [%0];" :: "r"(a) : "memory")
#define MBAR_WAIT(a, ph) do { \
    uint32_t _m = (a), _p = (ph), _d; \
    asm volatile("{ .reg .pred p; mbarrier.try_wait.parity.acquire.cta.shared::cta.b64 p, [%1], %2; selp.b32 %0,1,0,p; }" \
        : "=r"(_d) : "r"(_m), "r"(_p) : "memory"); \
    if (!_d) { \
        asm volatile("{ .reg .pred P1; WL_%=: mbarrier.try_wait.parity.acquire.cta.shared::cta.b64 P1, [%0], %1, 0x989680; @P1 bra.uni WD_%=; bra.uni WL_%=; WD_%=: }" \
            :: "r"(_m), "r"(_p) : "memory"); \
    } } while (0)

__device__ __forceinline__ void bulk_cp(uint32_t dst, const char* src, uint32_t bytes, uint32_t mb) {
    asm volatile("cp.async.bulk.shared::cluster.global.mbarrier::complete_tx::bytes [%0], [%1], %2, [%3];"
        :: "r"(dst), "l"(src), "r"(bytes), "r"(mb) : "memory");
}

// wide rows 128B: chunk xor key r&7
__device__ __forceinline__ uint32_t inrowA(int r, int b) {
    return (uint32_t)(((((b >> 4) ^ (r & 7)) << 4)) | (b & 15));
}
// narrow rows 64B: chunk xor key (r>>1)&3
__device__ __forceinline__ uint32_t inrowB(int r, int b) {
    return (uint32_t)(((((b >> 4) ^ ((r >> 1) & 3)) << 4)) | (b & 15));
}
__device__ __forceinline__ size_t off_b(int row, int k) {
    return (size_t)(k >> 5) * BCH + (size_t)row * 64 + inrowB(row, (k & 31) * 2);
}
__device__ __forceinline__ size_t off_n(int row, int k) {
    return (size_t)(k >> 5) * HCH + (size_t)row * 64 + inrowB(row, (k & 31) * 2);
}
__device__ __forceinline__ void store_h_smem(char* hbase, int lrow, int k, float x, float y) {
    uint32_t H, L; split2(x, y, H, L);
    char* row = hbase + (size_t)((k >> 5) * 16384 + lrow * 128);
    *(uint32_t*)(row + inrowA(lrow, (k & 31) * 2)) = H;
    *(uint32_t*)(row + inrowA(lrow, 64 + (k & 31) * 2)) = L;
}

__device__ __forceinline__ void ring_init(uint32_t mb, int tid, int nwarp) {
    if (tid == 0) {
#pragma unroll
        for (int s = 0; s < NSTAGE; ++s) {
            MBAR_INIT(mb + s * 8, 1);
            MBAR_INIT(mb + 24 + s * 8, (uint32_t)nwarp);
        }
    }
}

// ---------------- proj GEMM (256 thr, 8 warps): A hi-only, 1-pass, B half ----

__device__ __forceinline__ void issue_p(uint32_t sb, uint32_t mb, int st,
    const char* Aimg, const char* Bimg, int c)
{
    const uint32_t buf = sb + (uint32_t)st * STAGE1;
    MBAR_EXPECT(mb + st * 8, 16384u);
    bulk_cp(buf,          Aimg + (size_t)c * HCH, 8192, mb + st * 8);
    bulk_cp(buf + OFF_B1, Bimg + (size_t)c * BCH, 8192, mb + st * 8);
}

__device__ __forceinline__ void gemm_proj(uint32_t sb, uint32_t mb,
    const char* __restrict__ Aimg, const char* __restrict__ Bimg,
    float acc[2][8][4])
{
    const int tid = threadIdx.x;
    const int lane = tid & 31, wid = tid >> 5;
    const int wm = wid >> 1, wn = wid & 1;

#pragma unroll
    for (int mt = 0; mt < 2; ++mt)
#pragma unroll
        for (int nt = 0; nt < 8; ++nt)
#pragma unroll
            for (int i = 0; i < 4; ++i) acc[mt][nt][i] = 0.f;

    __syncthreads();
    ring_init(mb, tid, 8);
    __syncthreads();
    if (tid == 0) { issue_p(sb, mb, 0, Aimg, Bimg, 0); issue_p(sb, mb, 1, Aimg, Bimg, 1); }

    const uint32_t a_base = (uint32_t)(wm*32 + (lane & 15)) * 64;
    const uint32_t a_kh   = lane >> 4;
    const uint32_t axr    = (lane >> 1) & 3;
    const uint32_t b_row  = (lane & 7) + ((lane & 16) >> 1);
    const uint32_t b_base = ((uint32_t)(wn*64) + b_row) * 64;
    const uint32_t b_kh   = (lane >> 3) & 1;
    const uint32_t bxr    = (lane & 6) >> 1;

#pragma unroll
    for (int c = 0; c < 8; ++c) {
        const int st = c % NSTAGE;
        if (tid == 0 && c + 2 < 8) {
            const int cn = c + 2, st2 = cn % NSTAGE;
            if (cn >= NSTAGE) { MBAR_WAIT(mb + 24 + st2 * 8, ((cn - NSTAGE) / NSTAGE) & 1); }
            issue_p(sb, mb, st2, Aimg, Bimg, cn);
        }
        MBAR_WAIT(mb + st * 8, (c / NSTAGE) & 1);
        const uint32_t buf = sb + (uint32_t)st * STAGE1;
#pragma unroll
        for (int s = 0; s < 2; ++s) {
            const uint32_t ax = (((uint32_t)s*2 + a_kh) ^ axr) << 4;
            const uint32_t bx = (((uint32_t)s*2 + b_kh) ^ bxr) << 4;
            uint32_t ah[2][4];
#pragma unroll
            for (int mt = 0; mt < 2; ++mt)
                ldsm_x4(ah[mt], buf + a_base + (uint32_t)mt*1024 + ax);
#pragma unroll
            for (int half = 0; half < 2; ++half) {
                uint32_t bh[2][4];
#pragma unroll
                for (int p = 0; p < 2; ++p)
                    ldsm_x4(bh[p], buf + OFF_B1 + b_base + (uint32_t)(half*2 + p)*1024 + bx);
#pragma unroll
                for (int mt = 0; mt < 2; ++mt)
#pragma unroll
                    for (int p = 0; p < 2; ++p)
#pragma unroll
                        for (int q = 0; q < 2; ++q)
                            mma16816(acc[mt][half*4 + p*2 + q], ah[mt], &bh[p][q*2]);
            }
        }
        if (lane == 0) MBAR_ARRIVE(mb + 24 + st * 8);
    }
}

// ---------------- fused GEMMs (512 thr, 16 warps, 4x4 warp grid) -------------

__device__ __forceinline__ void issue_f1(uint32_t sb, uint32_t mb, int st,
    const char* Aimg, const char* Bimg, int c)
{
    const uint32_t buf = sb + (uint32_t)st * STAGEF;
    MBAR_EXPECT(mb + st * 8, 24576u);
    bulk_cp(buf,          Aimg + (size_t)c * HCH, 8192, mb + st * 8);
    bulk_cp(buf + OFF_BF, Bimg + (size_t)c * BCH, 16384, mb + st * 8);
}

// phase1: C[128,256] = Ah[128,256] @ Bh[256,256]^T-rows, single pass.
__device__ __forceinline__ void gemm_f1(uint32_t sb, uint32_t mb,
    const char* __restrict__ Aimg, const char* __restrict__ Bimg,
    float acc[2][8][4])
{
    const int tid = threadIdx.x;
    const int lane = tid & 31, wid = tid >> 5;
    const int wm = wid >> 2, wn = wid & 3;

#pragma unroll
    for (int mt = 0; mt < 2; ++mt)
#pragma unroll
        for (int nt = 0; nt < 8; ++nt)
#pragma unroll
            for (int i = 0; i < 4; ++i) acc[mt][nt][i] = 0.f;

    __syncthreads();
    ring_init(mb, tid, 16);
    __syncthreads();
    if (tid == 0) { issue_f1(sb, mb, 0, Aimg, Bimg, 0); issue_f1(sb, mb, 1, Aimg, Bimg, 1); }

    const uint32_t a_base = (uint32_t)(wm*32 + (lane & 15)) * 64;
    const uint32_t a_kh   = lane >> 4;
    const uint32_t axr    = (lane >> 1) & 3;
    const uint32_t b_row  = (lane & 7) + ((lane & 16) >> 1);
    const uint32_t b_base = ((uint32_t)(wn*64) + b_row) * 64;
    const uint32_t b_kh   = (lane >> 3) & 1;
    const uint32_t bxr    = (lane & 6) >> 1;

#pragma unroll
    for (int c = 0; c < 8; ++c) {
        const int st = c % NSTAGE;
        if (tid == 0 && c + 2 < 8) {
            const int cn = c + 2, st2 = cn % NSTAGE;
            if (cn >= NSTAGE) { MBAR_WAIT(mb + 24 + st2 * 8, ((cn - NSTAGE) / NSTAGE) & 1); }
            issue_f1(sb, mb, st2, Aimg, Bimg, cn);
        }
        MBAR_WAIT(mb + st * 8, (c / NSTAGE) & 1);
        const uint32_t buf = sb + (uint32_t)st * STAGEF;
#pragma unroll
        for (int s = 0; s < 2; ++s) {
            const uint32_t ax = (((uint32_t)s*2 + a_kh) ^ axr) << 4;
            const uint32_t bx = (((uint32_t)s*2 + b_kh) ^ bxr) << 4;
            uint32_t ah[2][4];
#pragma unroll
            for (int mt = 0; mt < 2; ++mt)
                ldsm_x4(ah[mt], buf + a_base + (uint32_t)mt*1024 + ax);
#pragma unroll
            for (int half = 0; half < 2; ++half) {
                uint32_t bh[2][4];
#pragma unroll
                for (int p = 0; p < 2; ++p)
                    ldsm_x4(bh[p], buf + OFF_BF + b_base + (uint32_t)(half*2 + p)*1024 + bx);
#pragma unroll
                for (int mt = 0; mt < 2; ++mt)
#pragma unroll
                    for (int p = 0; p < 2; ++p)
#pragma unroll
                        for (int q = 0; q < 2; ++q)
                            mma16816(acc[mt][half*4 + p*2 + q], ah[mt], &bh[p][q*2]);
            }
        }
        if (lane == 0) MBAR_ARRIVE(mb + 24 + st * 8);
    }
}

__device__ __forceinline__ void issue_f2(uint32_t sb, uint32_t mb, int st,
    const char* Bimg, int c)
{
    MBAR_EXPECT(mb + st * 8, 16384u);
    bulk_cp(sb + (uint32_t)st * STAGEF + OFF_BF, Bimg + (size_t)c * BCH, 16384, mb + st * 8);
}

// phase2: C[128,256] = Hsplit(smem) @ Woh[256,256]^T-rows, 2-pass.
__device__ __forceinline__ void gemm_f2(uint32_t sb, uint32_t mb, uint32_t himg,
    const char* __restrict__ Bimg, float acc[2][8][4])
{
    const int tid = threadIdx.x;
    const int lane = tid & 31, wid = tid >> 5;
    const int wm = wid >> 2, wn = wid & 3;

#pragma unroll
    for (int mt = 0; mt < 2; ++mt)
#pragma unroll
        for (int nt = 0; nt < 8; ++nt)
#pragma unroll
            for (int i = 0; i < 4; ++i) acc[mt][nt][i] = 0.f;

    __syncthreads();   // h-image writes + prior ring use complete
    ring_init(mb, tid, 16);
    __syncthreads();
    if (tid == 0) { issue_f2(sb, mb, 0, Bimg, 0); issue_f2(sb, mb, 1, Bimg, 1); }

    const uint32_t xr     = lane & 7;
    const uint32_t a_base = (uint32_t)(wm*32 + (lane & 15)) * 128;
    const uint32_t a_kh   = lane >> 4;
    const uint32_t b_row  = (lane & 7) + ((lane & 16) >> 1);
    const uint32_t b_base = ((uint32_t)(wn*64) + b_row) * 64;
    const uint32_t b_kh   = (lane >> 3) & 1;
    const uint32_t bxr    = (lane & 6) >> 1;

#pragma unroll
    for (int c = 0; c < 8; ++c) {
        const int st = c % NSTAGE;
        if (tid == 0 && c + 2 < 8) {
            const int cn = c + 2, st2 = cn % NSTAGE;
            if (cn >= NSTAGE) { MBAR_WAIT(mb + 24 + st2 * 8, ((cn - NSTAGE) / NSTAGE) & 1); }
            issue_f2(sb, mb, st2, Bimg, cn);
        }
        MBAR_WAIT(mb + st * 8, (c / NSTAGE) & 1);
        const uint32_t bufB = sb + (uint32_t)st * STAGEF + OFF_BF;
        const uint32_t abuf = himg + (uint32_t)c * 16384;
#pragma unroll
        for (int s = 0; s < 2; ++s) {
            const uint32_t ach = (uint32_t)s*2 + a_kh;
            const uint32_t ax_h = ((ach ^ xr) << 4), ax_l = (((ach + 4) ^ xr) << 4);
            const uint32_t bx   = (((uint32_t)s*2 + b_kh) ^ bxr) << 4;
            uint32_t ah[2][4], al[2][4];
#pragma unroll
            for (int mt = 0; mt < 2; ++mt) {
                const uint32_t ao = abuf + a_base + (uint32_t)mt*2048;
                ldsm_x4(ah[mt], ao + ax_h);
                ldsm_x4(al[mt], ao + ax_l);
            }
#pragma unroll
            for (int half = 0; half < 2; ++half) {
                uint32_t bh[2][4];
#pragma unroll
                for (int p = 0; p < 2; ++p)
                    ldsm_x4(bh[p], bufB + b_base + (uint32_t)(half*2 + p)*1024 + bx);
#pragma unroll
                for (int mt = 0; mt < 2; ++mt)
#pragma unroll
                    for (int p = 0; p < 2; ++p)
#pragma unroll
                        for (int q = 0; q < 2; ++q)
                            mma16816(acc[mt][half*4 + p*2 + q], ah[mt], &bh[p][q*2]);
#pragma unroll
                for (int mt = 0; mt < 2; ++mt)
#pragma unroll
                    for (int p = 0; p < 2; ++p)
#pragma unroll
                        for (int q = 0; q < 2; ++q)
                            mma16816(acc[mt][half*4 + p*2 + q], al[mt], &bh[p][q*2]);
            }
        }
        if (lane == 0) MBAR_ARRIVE(mb + 24 + st * 8);
    }
}

// ---------------- prep kernels ----------------

extern "C" __global__ void psplit_kernel(const float* __restrict__ pair)
{
    const size_t i = ((size_t)blockIdx.x * 256 + threadIdx.x) * 4;
    const int m = (int)(i >> 8), col = (int)(i & 255);
    float4 v = *(const float4*)(pair + i);
    uint32_t h01 = pack_h2(__float2half_rn(v.x), __float2half_rn(v.y));
    uint32_t h23 = pack_h2(__float2half_rn(v.z), __float2half_rn(v.w));
    *(uint2*)((char*)g_P + off_n(m, col)) = make_uint2(h01, h23);
}

extern "C" __global__ void wprep_kernel(const float* __restrict__ Wa,
                                        const float* __restrict__ Wb,
                                        const float* __restrict__ Wg,
                                        const float* __restrict__ Wo)
{
    const float* Ws[4] = {Wa, Wb, Wg, Wo};
    const int d = blockIdx.x, c = threadIdx.x;
    const size_t off = off_b(d, c);
#pragma unroll
    for (int w = 0; w < 4; ++w) {
        __half h = __float2half_rn(Ws[w][c*256 + d]);
        *(__half*)((char*)g_W + (size_t)w * SLB + off) = h;
    }
}

// ---------------- main kernels ----------------

// grid (6, 1024): x = w*2 + nt, y = m-tile. 256 thr, 2 CTAs/SM.
extern "C" __global__ void __launch_bounds__(256, 2)
proj_kernel(const float* __restrict__ ba, const float* __restrict__ bb,
            const float* __restrict__ bg)
{
    extern __shared__ char smem[];
    const uint32_t sb = smem_u32(smem);
    const int w = blockIdx.x >> 1, nt = blockIdx.x & 1;
    const int m0 = blockIdx.y * 128;

    float acc[2][8][4];
    gemm_proj(sb, sb + OFF_MBP,
              (const char*)g_P + (size_t)m0*64,
              (const char*)g_W + (size_t)w*SLB + (size_t)nt*8192,
              acc);
    __syncthreads();

    const float* bias = (w == 0) ? ba : ((w == 1) ? bb : bg);
    const int wid = threadIdx.x >> 5, lane = threadIdx.x & 31;
    const int wm = wid >> 1, wn = wid & 1;
    const int g = lane >> 2, qc = lane & 3;

    if (w == 1) {
        float* stg = (float*)smem + wid * 2080;  // 32*65
#pragma unroll
        for (int mt = 0; mt < 2; ++mt)
#pragma unroll
            for (int ntl = 0; ntl < 8; ++ntl) {
                const int rm = mt*16 + g, cn = ntl*8 + 2*qc;
                float2 bv = *(const float2*)(bias + nt*128 + wn*64 + cn);
                stg[rm*65 + cn]           = acc[mt][ntl][0] + bv.x;
                stg[rm*65 + cn + 1]       = acc[mt][ntl][1] + bv.y;
                stg[(rm + 8)*65 + cn]     = acc[mt][ntl][2] + bv.x;
                stg[(rm + 8)*65 + cn + 1] = acc[mt][ntl][3] + bv.y;
            }
        __syncwarp();
        const int slice = m0 >> 8;
        const int j0 = (m0 & 255) + wm * 32;
        const int m2 = 2 * (lane & 15);
        const int j = j0 + m2;
        char* base = (char*)g_B + (size_t)slice * SLB;
        for (int r = lane >> 4; r < 64; r += 2) {
            const int l = nt*128 + wn*64 + r;
            uint32_t H = pack_h2(__float2half_rn(stg[m2*65 + r]),
                                 __float2half_rn(stg[(m2 + 1)*65 + r]));
            *(uint32_t*)(base + off_b(l, j)) = H;
        }
    } else {
#pragma unroll
        for (int mt = 0; mt < 2; ++mt) {
            const int R0 = m0 + wm*32 + mt*16 + g;
#pragma unroll
            for (int ntl = 0; ntl < 8; ++ntl) {
                const int col = nt*128 + wn*64 + ntl*8 + 2*qc;
                float2 bv = *(const float2*)(bias + col);
                float v0 = acc[mt][ntl][0] + bv.x, v1 = acc[mt][ntl][1] + bv.y;
                float v2 = acc[mt][ntl][2] + bv.x, v3 = acc[mt][ntl][3] + bv.y;
                if (w == 2) {
                    v0 = 1.f/(1.f + __expf(-v0)); v1 = 1.f/(1.f + __expf(-v1));
                    v2 = 1.f/(1.f + __expf(-v2)); v3 = 1.f/(1.f + __expf(-v3));
                    *(uint32_t*)(g_G + (size_t)R0*256 + col) =
                        pack_h2(__float2half_rn(v0), __float2half_rn(v1));
                    *(uint32_t*)(g_G + (size_t)(R0 + 8)*256 + col) =
                        pack_h2(__float2half_rn(v2), __float2half_rn(v3));
                } else {
                    *(uint32_t*)((char*)g_A + off_n(R0, col)) =
                        pack_h2(__float2half_rn(v0), __float2half_rn(v1));
                    *(uint32_t*)((char*)g_A + off_n(R0 + 8, col)) =
                        pack_h2(__float2half_rn(v2), __float2half_rn(v3));
                }
            }
        }
    }
}

// grid (2, 512): x = jt, y = slice. 512 thr fused tri+out.
extern "C" __global__ void __launch_bounds__(512)
fused_kernel(const float* __restrict__ bo, float* __restrict__ out)
{
    extern __shared__ char smem[];
    const uint32_t sb = smem_u32(smem);
    const uint32_t mb = sb + OFF_MBF;
    const uint32_t himg = sb + OFF_HIMG;
    char* hptr = smem + OFF_HIMG;
    const int jt = blockIdx.x, slice = blockIdx.y;

    const int wid = threadIdx.x >> 5, lane = threadIdx.x & 31;
    const int wm = wid >> 2, wn = wid & 3;
    const int g = lane >> 2, qc = lane & 3;
    const int mbase = slice*256 + jt*128;

    // ---- phase 1: h = gate * (a_s @ b_s) -> smem split image ----
    {
        float acc[2][8][4];
        gemm_f1(sb, mb,
                (const char*)g_A + (size_t)mbase*64,
                (const char*)g_B + (size_t)slice*SLB,
                acc);
#pragma unroll
        for (int mt = 0; mt < 2; ++mt) {
            const int lr = wm*32 + mt*16 + g;
            const int Rg = mbase + lr;
#pragma unroll
            for (int ntl = 0; ntl < 8; ++ntl) {
                const int col = wn*64 + ntl*8 + 2*qc;
                float2 g0 = __half22float2(*(const __half2*)(g_G + (size_t)Rg*256 + col));
                float2 g1 = __half22float2(*(const __half2*)(g_G + (size_t)(Rg + 8)*256 + col));
                store_h_smem(hptr, lr,     col, acc[mt][ntl][0]*g0.x, acc[mt][ntl][1]*g0.y);
                store_h_smem(hptr, lr + 8, col, acc[mt][ntl][2]*g1.x, acc[mt][ntl][3]*g1.y);
            }
        }
    }

    // ---- phase 2: out = h @ Wo^T-rows + bo ----
    {
        float acc[2][8][4];
        gemm_f2(sb, mb, himg, (const char*)g_W + (size_t)3*SLB, acc);
#pragma unroll
        for (int mt = 0; mt < 2; ++mt) {
            const int R0 = mbase + wm*32 + mt*16 + g;
#pragma unroll
            for (int ntl = 0; ntl < 8; ++ntl) {
                const int col = wn*64 + ntl*8 + 2*qc;
                float2 bv = *(const float2*)(bo + col);
                *(float2*)(out + (size_t)R0*256 + col) =
                    make_float2(acc[mt][ntl][0] + bv.x, acc[mt][ntl][1] + bv.y);
                *(float2*)(out + (size_t)(R0 + 8)*256 + col) =
                    make_float2(acc[mt][ntl][2] + bv.x, acc[mt][ntl][3] + bv.y);
            }
        }
    }
}

extern "C" void kernel_launch(void* const* d_in, const int* in_sizes, int n_in,
                              void* d_out, int out_size)
{
    const float* pair = (const float*)d_in[0];
    const float* Wa   = (const float*)d_in[1];
    const float* ba   = (const float*)d_in[2];
    const float* Wb   = (const float*)d_in[3];
    const float* bb   = (const float*)d_in[4];
    const float* Wg   = (const float*)d_in[5];
    const float* bg   = (const float*)d_in[6];
    const float* Wo   = (const float*)d_in[7];
    const float* bo   = (const float*)d_in[8];
    float* out = (float*)d_out;

    cudaFuncSetAttribute(proj_kernel,  cudaFuncAttributeMaxDynamicSharedMemorySize, SMEM_P);
    cudaFuncSetAttribute(fused_kernel, cudaFuncAttributeMaxDynamicSharedMemorySize, SMEM_F);

    wprep_kernel <<<256,   256>>>(Wa, Wb, Wg, Wo);
    psplit_kernel<<<32768, 256>>>(pair);
    proj_kernel <<<dim3(6, 1024), 256, SMEM_P>>>(ba, bb, bg);
    fused_kernel<<<dim3(2, 512),  512, SMEM_F>>>(bo, out);
}